// round 8
// baseline (speedup 1.0000x reference)
#include <cuda_runtime.h>
#include <cuda_bf16.h>
#include <math.h>
#include <stdint.h>

#define B_   16
#define L_   1024
#define C_   64
#define K_   10
#define H_   1024
#define M_   (B_*L_)        /* 16384 rows */
#define NOUT 1024           /* active half of COUT=2048 */
#define COUT_ 2048

/* scratch (allocation-free rule: __device__ globals) */
__device__ __nv_bfloat16 g_ha_hi[M_ * H_];   /* 32 MB */
__device__ __nv_bfloat16 g_ha_lo[M_ * H_];   /* 32 MB */
__device__ __nv_bfloat16 g_w2_hi[NOUT * H_]; /*  2 MB: [n][k] */
__device__ __nv_bfloat16 g_w2_lo[NOUT * H_]; /*  2 MB */
__device__ float g_nn[M_ * NOUT];            /* 64 MB */
__device__ float g_part[2048];

/* ---------------- helpers ---------------- */
__device__ __forceinline__ uint32_t smem_u32(const void* p) {
    uint32_t a;
    asm("{ .reg .u64 t; cvta.to.shared.u64 t, %1; cvt.u32.u64 %0, t; }" : "=r"(a) : "l"(p));
    return a;
}
#define CPA16(dst, src) asm volatile("cp.async.cg.shared.global [%0], [%1], 16;" :: "r"(dst), "l"(src))
#define CPA_COMMIT()    asm volatile("cp.async.commit_group;")
#define CPA_WAIT(n)     asm volatile("cp.async.wait_group %0;" :: "n"(n) : "memory")

__device__ __forceinline__ void ldm_x4(uint32_t& r0, uint32_t& r1, uint32_t& r2, uint32_t& r3,
                                       uint32_t addr) {
    asm volatile("ldmatrix.sync.aligned.m8n8.x4.shared.b16 {%0,%1,%2,%3}, [%4];"
                 : "=r"(r0), "=r"(r1), "=r"(r2), "=r"(r3) : "r"(addr));
}
__device__ __forceinline__ void mma_bf16(float* d, const uint32_t* a, const uint32_t* b) {
    asm volatile("mma.sync.aligned.m16n8k16.row.col.f32.bf16.bf16.f32 "
                 "{%0,%1,%2,%3}, {%4,%5,%6,%7}, {%8,%9}, {%0,%1,%2,%3};"
                 : "+f"(d[0]), "+f"(d[1]), "+f"(d[2]), "+f"(d[3])
                 : "r"(a[0]), "r"(a[1]), "r"(a[2]), "r"(a[3]), "r"(b[0]), "r"(b[1]));
}

__device__ __forceinline__ float gelu_tanh(float x) {
    const float k0 = 0.7978845608028654f, k1 = 0.044715f;
    float t = tanhf(k0 * (x + k1 * x * x * x));
    return 0.5f * x * (1.0f + t);
}

/* ------------------------------------------------------------------ */
/* w2 transpose+split: hi/lo bf16 of w2[k][1024+n] at [n][k]           */
/* ------------------------------------------------------------------ */
__global__ __launch_bounds__(256) void w2t_kernel(const float* __restrict__ w2)
{
    __shared__ float t[32][33];
    int k0 = blockIdx.y * 32, n0 = blockIdx.x * 32;
    int tx = threadIdx.x & 31, ty = threadIdx.x >> 5;   /* 32 x 8 */
    #pragma unroll
    for (int j = 0; j < 32; j += 8)
        t[ty + j][tx] = w2[(size_t)(k0 + ty + j) * COUT_ + 1024 + n0 + tx];
    __syncthreads();
    #pragma unroll
    for (int j = 0; j < 32; j += 8) {
        float v = t[tx][ty + j];
        __nv_bfloat16 hi = __float2bfloat16(v);
        __nv_bfloat16 lo = __float2bfloat16(v - __bfloat162float(hi));
        size_t idx = (size_t)(n0 + ty + j) * H_ + k0 + tx;
        g_w2_hi[idx] = hi;
        g_w2_lo[idx] = lo;
    }
}

/* ------------------------------------------------------------------ */
/* GEMM1: h = gelu(z_in @ w1 + b1), K truncated to 32 (mask zeroes top)*/
/* epilogue stores bf16 hi + lo                                        */
/* ------------------------------------------------------------------ */
__global__ __launch_bounds__(256) void gemm1_kernel(
    const float* __restrict__ z, const float* __restrict__ mask,
    const float* __restrict__ w1, const float* __restrict__ b1)
{
    __shared__ float zs[32][64];
    __shared__ float ws[32][128];

    const int m0 = blockIdx.y * 64;
    const int n0 = blockIdx.x * 128;
    const int tid = threadIdx.x;

    #pragma unroll
    for (int s = 0; s < 2; s++) {
        int idx = tid + 256 * s;
        int row = idx >> 3, q = idx & 7;
        float4 v = *reinterpret_cast<const float4*>(z + (size_t)(m0 + row) * C_ + q * 4);
        int c = q * 4;
        zs[c + 0][row] = v.x * __ldg(mask + c + 0);
        zs[c + 1][row] = v.y * __ldg(mask + c + 1);
        zs[c + 2][row] = v.z * __ldg(mask + c + 2);
        zs[c + 3][row] = v.w * __ldg(mask + c + 3);
    }
    #pragma unroll
    for (int s = 0; s < 4; s++) {
        int idx = tid + 256 * s;
        int c = idx >> 5, j = idx & 31;
        *reinterpret_cast<float4*>(&ws[c][j * 4]) =
            *reinterpret_cast<const float4*>(w1 + (size_t)c * H_ + n0 + j * 4);
    }
    __syncthreads();

    const int ty = tid >> 5, tx = tid & 31;
    float acc[8][4];
    #pragma unroll
    for (int i = 0; i < 8; i++)
        #pragma unroll
        for (int j = 0; j < 4; j++) acc[i][j] = 0.0f;

    #pragma unroll 8
    for (int c = 0; c < 32; c++) {
        float4 b4 = *reinterpret_cast<float4*>(&ws[c][tx * 4]);
        float a[8];
        *reinterpret_cast<float4*>(a)     = *reinterpret_cast<float4*>(&zs[c][ty * 8]);
        *reinterpret_cast<float4*>(a + 4) = *reinterpret_cast<float4*>(&zs[c][ty * 8 + 4]);
        #pragma unroll
        for (int i = 0; i < 8; i++) {
            acc[i][0] += a[i] * b4.x; acc[i][1] += a[i] * b4.y;
            acc[i][2] += a[i] * b4.z; acc[i][3] += a[i] * b4.w;
        }
    }

    float4 bb = *reinterpret_cast<const float4*>(b1 + n0 + tx * 4);
    #pragma unroll
    for (int i = 0; i < 8; i++) {
        int row = m0 + ty * 8 + i;
        float o[4];
        o[0] = gelu_tanh(acc[i][0] + bb.x);
        o[1] = gelu_tanh(acc[i][1] + bb.y);
        o[2] = gelu_tanh(acc[i][2] + bb.z);
        o[3] = gelu_tanh(acc[i][3] + bb.w);
        __nv_bfloat162 h0, h1, l0, l1;
        h0.x = __float2bfloat16(o[0]); h0.y = __float2bfloat16(o[1]);
        h1.x = __float2bfloat16(o[2]); h1.y = __float2bfloat16(o[3]);
        l0.x = __float2bfloat16(o[0] - __bfloat162float(h0.x));
        l0.y = __float2bfloat16(o[1] - __bfloat162float(h0.y));
        l1.x = __float2bfloat16(o[2] - __bfloat162float(h1.x));
        l1.y = __float2bfloat16(o[3] - __bfloat162float(h1.y));
        size_t off = (size_t)row * H_ + n0 + tx * 4;
        *reinterpret_cast<uint2*>(g_ha_hi + off) = make_uint2(*(uint32_t*)&h0, *(uint32_t*)&h1);
        *reinterpret_cast<uint2*>(g_ha_lo + off) = make_uint2(*(uint32_t*)&l0, *(uint32_t*)&l1);
    }
}

/* ------------------------------------------------------------------ */
/* GEMM2: 3xBF16 split-precision, BM=256 BN=128 BK=32, 512 threads     */
/* Per k-tile load A_hi,A_lo,B_hi,B_lo ONCE; 3 mma phases from smem:   */
/*   (A_hi,B_hi), (A_hi,B_lo), (A_lo,B_hi)                             */
/* 16 warps = 4(M) x 4(N), warp tile 64x32                             */
/* ------------------------------------------------------------------ */
#define G2_NT 32
#define ST_AHI 0
#define ST_ALO 16384
#define ST_BHI 32768
#define ST_BLO 40960
#define ST_SZ  49152
#define G2_SMEM (2 * ST_SZ)   /* 96 KB dynamic */

__global__ __launch_bounds__(512) void gemm2_mma_kernel(const float* __restrict__ b2)
{
    extern __shared__ __align__(16) char smem[];
    const uint32_t sb = smem_u32(smem);

    const int tid = threadIdx.x;
    const int wid = tid >> 5, lid = tid & 31;
    const int m0 = blockIdx.y * 256;
    const int n0 = blockIdx.x * 128;
    const int wm = (wid >> 2) * 64;
    const int wn = (wid & 3) * 32;

    const __nv_bfloat16* Ahi = g_ha_hi + (size_t)m0 * H_;
    const __nv_bfloat16* Alo = g_ha_lo + (size_t)m0 * H_;
    const __nv_bfloat16* Bhi = g_w2_hi + (size_t)n0 * H_;
    const __nv_bfloat16* Blo = g_w2_lo + (size_t)n0 * H_;

    /* load one K-tile: A 2x1024 + B 2x512 chunks of 16B = 3072 chunks */
    auto load_tile = [&](int kt, int b) {
        uint32_t base = sb + b * ST_SZ;
        #pragma unroll
        for (int s = 0; s < 6; s++) {
            int idx = tid + 512 * s;          /* 0..3071 */
            if (idx < 2048) {
                int i2 = idx & 1023;
                int row = i2 >> 2, seg = i2 & 3;
                uint32_t dst = (uint32_t)(row * 64 + ((seg ^ ((row >> 1) & 3)) << 4));
                const __nv_bfloat16* src = (idx < 1024) ? Ahi : Alo;
                uint32_t so = (idx < 1024) ? ST_AHI : ST_ALO;
                CPA16(base + so + dst, src + (size_t)row * H_ + kt * 32 + seg * 8);
            } else {
                int i2 = idx & 511;
                int row = i2 >> 2, seg = i2 & 3;
                uint32_t dst = (uint32_t)(row * 64 + ((seg ^ ((row >> 1) & 3)) << 4));
                const __nv_bfloat16* src = (idx < 2560) ? Bhi : Blo;
                uint32_t so = (idx < 2560) ? ST_BHI : ST_BLO;
                CPA16(base + so + dst, src + (size_t)row * H_ + kt * 32 + seg * 8);
            }
        }
        CPA_COMMIT();
    };

    float acc[4][4][4];
    #pragma unroll
    for (int i = 0; i < 4; i++)
        #pragma unroll
        for (int j = 0; j < 4; j++)
            #pragma unroll
            for (int q = 0; q < 4; q++) acc[i][j][q] = 0.0f;

    load_tile(0, 0);

    for (int kt = 0; kt < G2_NT; kt++) {
        const int b = kt & 1;
        if (kt + 1 < G2_NT) { load_tile(kt + 1, 1 - b); CPA_WAIT(1); }
        else                { CPA_WAIT(0); }
        __syncthreads();

        uint32_t stage = sb + b * ST_SZ;
        /* 3 phases: (Ahi,Bhi), (Ahi,Blo), (Alo,Bhi) */
        #pragma unroll
        for (int ph = 0; ph < 3; ph++) {
            uint32_t abase = stage + ((ph == 2) ? ST_ALO : ST_AHI);
            uint32_t bbase = stage + ((ph == 1) ? ST_BLO : ST_BHI);
            #pragma unroll
            for (int kh = 0; kh < 2; kh++) {
                uint32_t af[4][4];
                #pragma unroll
                for (int mt = 0; mt < 4; mt++) {
                    int row = wm + mt * 16 + (lid & 15);
                    int ch  = (kh * 2 + (lid >> 4)) ^ ((row >> 1) & 3);
                    ldm_x4(af[mt][0], af[mt][1], af[mt][2], af[mt][3],
                           abase + (uint32_t)(row * 64 + ch * 16));
                }
                uint32_t bfr[2][4];
                #pragma unroll
                for (int np = 0; np < 2; np++) {
                    int row = wn + np * 16 + ((lid >> 4) * 8) + (lid & 7);
                    int ch  = (kh * 2 + ((lid >> 3) & 1)) ^ ((row >> 1) & 3);
                    ldm_x4(bfr[np][0], bfr[np][1], bfr[np][2], bfr[np][3],
                           bbase + (uint32_t)(row * 64 + ch * 16));
                }
                #pragma unroll
                for (int mt = 0; mt < 4; mt++)
                    #pragma unroll
                    for (int nt = 0; nt < 4; nt++)
                        mma_bf16(acc[mt][nt], af[mt], &bfr[nt >> 1][(nt & 1) * 2]);
            }
        }
        __syncthreads();
    }

    /* epilogue: + bias, direct float2 stores */
    #pragma unroll
    for (int nt = 0; nt < 4; nt++) {
        int col = n0 + wn + nt * 8 + (lid & 3) * 2;
        float bx = __ldg(b2 + 1024 + col);
        float by = __ldg(b2 + 1024 + col + 1);
        #pragma unroll
        for (int mt = 0; mt < 4; mt++) {
            int r0 = m0 + wm + mt * 16 + (lid >> 2);
            float2 v0 = make_float2(acc[mt][nt][0] + bx, acc[mt][nt][1] + by);
            float2 v1 = make_float2(acc[mt][nt][2] + bx, acc[mt][nt][3] + by);
            *reinterpret_cast<float2*>(g_nn + (size_t)r0 * NOUT + col) = v0;
            *reinterpret_cast<float2*>(g_nn + (size_t)(r0 + 8) * NOUT + col) = v1;
        }
    }
}

/* ------------------------------------------------------------------ */
/* Postproc: per (row, c>=32) mixture-CDF math                         */
/* ------------------------------------------------------------------ */
__global__ __launch_bounds__(256) void post_kernel(
    const float* __restrict__ z, const float* __restrict__ mask,
    const float* __restrict__ sfv, const float* __restrict__ msfv,
    float* __restrict__ out)
{
    __shared__ float red[256];
    const int tid = threadIdx.x;
    const int rl = tid >> 5, cl = tid & 31;
    const int row = blockIdx.x * 8 + rl;
    const int c = 32 + cl;

    {
        float mlow = __ldg(mask + cl);
        out[(size_t)row * C_ + cl] = z[(size_t)row * C_ + cl] * mlow;
    }

    float p[32];
    {
        const float* pp = g_nn + (size_t)row * NOUT + cl * 32;
        #pragma unroll
        for (int q = 0; q < 32; q += 4) {
            float4 v = *reinterpret_cast<const float4*>(pp + q);
            p[q] = v.x; p[q+1] = v.y; p[q+2] = v.z; p[q+3] = v.w;
        }
    }

    const float zc = z[(size_t)row * C_ + c];
    const float maskv = __ldg(mask + c);
    const float cm = 1.0f - maskv;

    float sf = expf(__ldg(sfv + c));
    float t  = p[0] * cm;
    float ls = tanhf(p[1] / fmaxf(sf, 1.0f)) * sf * cm;

    float lp[K_], aa[K_], bbk[K_];
    float mx0 = -INFINITY, mxA = -INFINITY, mxB = -INFINITY;
    #pragma unroll
    for (int k = 0; k < K_; k++) { lp[k] = p[2 + k] * cm; mx0 = fmaxf(mx0, lp[k]); }
    #pragma unroll
    for (int k = 0; k < K_; k++) {
        float msf = expf(__ldg(msfv + c * K_ + k));
        float mls = tanhf(p[22 + k] / fmaxf(msf, 1.0f)) * msf * cm;
        float mt  = p[12 + k] * cm;
        float u   = (zc - mt) * expf(-mls);
        float e   = expf(-fabsf(u));
        float l1  = log1pf(e);
        float logsig = fminf(u, 0.0f) - l1;
        float sp     = fmaxf(u, 0.0f) + l1;
        aa[k]  = lp[k] + logsig;
        bbk[k] = lp[k] + u - mls - 2.0f * sp;
        mxA = fmaxf(mxA, aa[k]);
        mxB = fmaxf(mxB, bbk[k]);
    }
    float s0 = 0.0f, sA = 0.0f, sB = 0.0f;
    #pragma unroll
    for (int k = 0; k < K_; k++) {
        s0 += expf(lp[k] - mx0); sA += expf(aa[k] - mxA); sB += expf(bbk[k] - mxB);
    }
    float lse0 = mx0 + logf(s0);
    float lseA = mxA + logf(sA);
    float lseB = mxB + logf(sB);

    float log_cdf = lseA - lse0;
    float p_cdf   = expf(log_cdf);
    float z_logit = -logf(fmaxf(1.0f / p_cdf - 1.0f, 1e-22f));
    float mixt_ldj = -logf(fmaxf(p_cdf, 1e-22f)) - logf(fmaxf(1.0f - p_cdf, 1e-22f));
    float logistic_ldj = lseB - lse0;

    float zo = (z_logit + t) * expf(ls);
    zo = zo * cm + zc * maskv;
    out[(size_t)row * C_ + c] = zo;

    red[tid] = cm * (ls + mixt_ldj + logistic_ldj);
    __syncthreads();
    for (int s = 128; s > 0; s >>= 1) {
        if (tid < s) red[tid] += red[tid + s];
        __syncthreads();
    }
    if (tid == 0) g_part[blockIdx.x] = red[0];
}

__global__ __launch_bounds__(128) void reduce_kernel(float* __restrict__ out)
{
    __shared__ float red[128];
    const int b = blockIdx.x, tid = threadIdx.x;
    red[tid] = g_part[b * 128 + tid];
    __syncthreads();
    for (int s = 64; s > 0; s >>= 1) {
        if (tid < s) red[tid] += red[tid + s];
        __syncthreads();
    }
    if (tid == 0) out[(size_t)M_ * C_ + b] = red[0];
}

extern "C" void kernel_launch(void* const* d_in, const int* in_sizes, int n_in,
                              void* d_out, int out_size)
{
    const float* z    = (const float*)d_in[0];
    const float* mask = (const float*)d_in[1];
    const float* w1   = (const float*)d_in[2];
    const float* b1   = (const float*)d_in[3];
    const float* w2   = (const float*)d_in[4];
    const float* b2   = (const float*)d_in[5];
    const float* sfv  = (const float*)d_in[6];
    const float* msfv = (const float*)d_in[7];
    float* out = (float*)d_out;

    cudaFuncSetAttribute(gemm2_mma_kernel,
                         cudaFuncAttributeMaxDynamicSharedMemorySize, G2_SMEM);

    dim3 gt(NOUT / 32, H_ / 32);
    w2t_kernel<<<gt, 256>>>(w2);

    dim3 g1(H_ / 128, M_ / 64);
    gemm1_kernel<<<g1, 256>>>(z, mask, w1, b1);

    dim3 g2(NOUT / 128, M_ / 256);   /* (8, 64) = 512 CTAs */
    gemm2_mma_kernel<<<g2, 512, G2_SMEM>>>(b2);

    post_kernel<<<M_ / 8, 256>>>(z, mask, sfv, msfv, out);
    reduce_kernel<<<B_, 128>>>(out);
}

// round 10
// speedup vs baseline: 1.1404x; 1.1404x over previous
#include <cuda_runtime.h>
#include <cuda_bf16.h>
#include <math.h>
#include <stdint.h>

#define B_   16
#define L_   1024
#define C_   64
#define K_   10
#define H_   1024
#define M_   (B_*L_)        /* 16384 rows */
#define NOUT 1024           /* active half of COUT=2048 */
#define COUT_ 2048

/* scratch (allocation-free rule: __device__ globals) */
__device__ __nv_bfloat16 g_ha_hi[M_ * H_];   /* 32 MB */
__device__ __nv_bfloat16 g_ha_lo[M_ * H_];   /* 32 MB */
__device__ __nv_bfloat16 g_w2_hi[NOUT * H_]; /*  2 MB: [n][k] */
__device__ __nv_bfloat16 g_w2_lo[NOUT * H_]; /*  2 MB */
__device__ float g_nn[M_ * NOUT];            /* 64 MB */
__device__ float g_part[2048];

/* ---------------- helpers ---------------- */
__device__ __forceinline__ uint32_t smem_u32(const void* p) {
    uint32_t a;
    asm("{ .reg .u64 t; cvta.to.shared.u64 t, %1; cvt.u32.u64 %0, t; }" : "=r"(a) : "l"(p));
    return a;
}
#define CPA16(dst, src) asm volatile("cp.async.cg.shared.global [%0], [%1], 16;" :: "r"(dst), "l"(src))
#define CPA_COMMIT()    asm volatile("cp.async.commit_group;")
#define CPA_WAIT(n)     asm volatile("cp.async.wait_group %0;" :: "n"(n) : "memory")

__device__ __forceinline__ void ldm_x4(uint32_t& r0, uint32_t& r1, uint32_t& r2, uint32_t& r3,
                                       uint32_t addr) {
    asm volatile("ldmatrix.sync.aligned.m8n8.x4.shared.b16 {%0,%1,%2,%3}, [%4];"
                 : "=r"(r0), "=r"(r1), "=r"(r2), "=r"(r3) : "r"(addr));
}
__device__ __forceinline__ void mma_bf16(float* d, const uint32_t* a, const uint32_t* b) {
    asm volatile("mma.sync.aligned.m16n8k16.row.col.f32.bf16.bf16.f32 "
                 "{%0,%1,%2,%3}, {%4,%5,%6,%7}, {%8,%9}, {%0,%1,%2,%3};"
                 : "+f"(d[0]), "+f"(d[1]), "+f"(d[2]), "+f"(d[3])
                 : "r"(a[0]), "r"(a[1]), "r"(a[2]), "r"(a[3]), "r"(b[0]), "r"(b[1]));
}

__device__ __forceinline__ float gelu_tanh(float x) {
    const float k0 = 0.7978845608028654f, k1 = 0.044715f;
    float t = tanhf(k0 * (x + k1 * x * x * x));
    return 0.5f * x * (1.0f + t);
}

/* ------------------------------------------------------------------ */
/* w2 transpose+split: hi/lo bf16 of w2[k][1024+n] at [n][k]           */
/* ------------------------------------------------------------------ */
__global__ __launch_bounds__(256) void w2t_kernel(const float* __restrict__ w2)
{
    __shared__ float t[32][33];
    int k0 = blockIdx.y * 32, n0 = blockIdx.x * 32;
    int tx = threadIdx.x & 31, ty = threadIdx.x >> 5;   /* 32 x 8 */
    #pragma unroll
    for (int j = 0; j < 32; j += 8)
        t[ty + j][tx] = w2[(size_t)(k0 + ty + j) * COUT_ + 1024 + n0 + tx];
    __syncthreads();
    #pragma unroll
    for (int j = 0; j < 32; j += 8) {
        float v = t[tx][ty + j];
        __nv_bfloat16 hi = __float2bfloat16(v);
        __nv_bfloat16 lo = __float2bfloat16(v - __bfloat162float(hi));
        size_t idx = (size_t)(n0 + ty + j) * H_ + k0 + tx;
        g_w2_hi[idx] = hi;
        g_w2_lo[idx] = lo;
    }
}

/* ------------------------------------------------------------------ */
/* GEMM1: h = gelu(z_in @ w1 + b1), K truncated to 32 (mask zeroes top)*/
/* epilogue stores bf16 hi + lo                                        */
/* ------------------------------------------------------------------ */
__global__ __launch_bounds__(256) void gemm1_kernel(
    const float* __restrict__ z, const float* __restrict__ mask,
    const float* __restrict__ w1, const float* __restrict__ b1)
{
    __shared__ float zs[32][64];
    __shared__ float ws[32][128];

    const int m0 = blockIdx.y * 64;
    const int n0 = blockIdx.x * 128;
    const int tid = threadIdx.x;

    #pragma unroll
    for (int s = 0; s < 2; s++) {
        int idx = tid + 256 * s;
        int row = idx >> 3, q = idx & 7;
        float4 v = *reinterpret_cast<const float4*>(z + (size_t)(m0 + row) * C_ + q * 4);
        int c = q * 4;
        zs[c + 0][row] = v.x * __ldg(mask + c + 0);
        zs[c + 1][row] = v.y * __ldg(mask + c + 1);
        zs[c + 2][row] = v.z * __ldg(mask + c + 2);
        zs[c + 3][row] = v.w * __ldg(mask + c + 3);
    }
    #pragma unroll
    for (int s = 0; s < 4; s++) {
        int idx = tid + 256 * s;
        int c = idx >> 5, j = idx & 31;
        *reinterpret_cast<float4*>(&ws[c][j * 4]) =
            *reinterpret_cast<const float4*>(w1 + (size_t)c * H_ + n0 + j * 4);
    }
    __syncthreads();

    const int ty = tid >> 5, tx = tid & 31;
    float acc[8][4];
    #pragma unroll
    for (int i = 0; i < 8; i++)
        #pragma unroll
        for (int j = 0; j < 4; j++) acc[i][j] = 0.0f;

    #pragma unroll 8
    for (int c = 0; c < 32; c++) {
        float4 b4 = *reinterpret_cast<float4*>(&ws[c][tx * 4]);
        float a[8];
        *reinterpret_cast<float4*>(a)     = *reinterpret_cast<float4*>(&zs[c][ty * 8]);
        *reinterpret_cast<float4*>(a + 4) = *reinterpret_cast<float4*>(&zs[c][ty * 8 + 4]);
        #pragma unroll
        for (int i = 0; i < 8; i++) {
            acc[i][0] += a[i] * b4.x; acc[i][1] += a[i] * b4.y;
            acc[i][2] += a[i] * b4.z; acc[i][3] += a[i] * b4.w;
        }
    }

    float4 bb = *reinterpret_cast<const float4*>(b1 + n0 + tx * 4);
    #pragma unroll
    for (int i = 0; i < 8; i++) {
        int row = m0 + ty * 8 + i;
        float o[4];
        o[0] = gelu_tanh(acc[i][0] + bb.x);
        o[1] = gelu_tanh(acc[i][1] + bb.y);
        o[2] = gelu_tanh(acc[i][2] + bb.z);
        o[3] = gelu_tanh(acc[i][3] + bb.w);
        __nv_bfloat162 h0, h1, l0, l1;
        h0.x = __float2bfloat16(o[0]); h0.y = __float2bfloat16(o[1]);
        h1.x = __float2bfloat16(o[2]); h1.y = __float2bfloat16(o[3]);
        l0.x = __float2bfloat16(o[0] - __bfloat162float(h0.x));
        l0.y = __float2bfloat16(o[1] - __bfloat162float(h0.y));
        l1.x = __float2bfloat16(o[2] - __bfloat162float(h1.x));
        l1.y = __float2bfloat16(o[3] - __bfloat162float(h1.y));
        size_t off = (size_t)row * H_ + n0 + tx * 4;
        *reinterpret_cast<uint2*>(g_ha_hi + off) = make_uint2(*(uint32_t*)&h0, *(uint32_t*)&h1);
        *reinterpret_cast<uint2*>(g_ha_lo + off) = make_uint2(*(uint32_t*)&l0, *(uint32_t*)&l1);
    }
}

/* ------------------------------------------------------------------ */
/* GEMM2: 3xBF16 split-precision, BM=128 BN=128 BK=32, 256 threads     */
/* Per k-tile load A_hi,A_lo,B_hi,B_lo ONCE (32KB stage, 2x buffered); */
/* 3 mma phases from smem: (A_hi,B_hi), (A_hi,B_lo), (A_lo,B_hi)       */
/* 8 warps = 2(M) x 4(N), warp tile 64x32 (R6-verified fragment code)  */
/* ------------------------------------------------------------------ */
#define G2_NT 32
#define ST_AHI 0
#define ST_ALO 8192
#define ST_BHI 16384
#define ST_BLO 24576
#define ST_SZ  32768
#define G2_SMEM (2 * ST_SZ)   /* 64 KB dynamic */

__global__ __launch_bounds__(256) void gemm2_mma_kernel(const float* __restrict__ b2)
{
    extern __shared__ __align__(16) char smem[];
    const uint32_t sb = smem_u32(smem);

    const int tid = threadIdx.x;
    const int wid = tid >> 5, lid = tid & 31;
    const int m0 = blockIdx.y * 128;
    const int n0 = blockIdx.x * 128;
    const int wm = (wid >> 2) * 64;
    const int wn = (wid & 3) * 32;

    const __nv_bfloat16* srcs[4] = {
        g_ha_hi + (size_t)m0 * H_,
        g_ha_lo + (size_t)m0 * H_,
        g_w2_hi + (size_t)n0 * H_,
        g_w2_lo + (size_t)n0 * H_
    };

    /* load one K-tile: 4 parts x 512 chunks of 16B = 2048 chunks */
    auto load_tile = [&](int kt, int b) {
        uint32_t base = sb + b * ST_SZ;
        #pragma unroll
        for (int s = 0; s < 8; s++) {
            int idx = tid + 256 * s;          /* 0..2047 */
            int part = idx >> 9;              /* 0..3 */
            int i2 = idx & 511;
            int row = i2 >> 2, seg = i2 & 3;
            uint32_t dst = (uint32_t)(part * 8192 + row * 64 + ((seg ^ ((row >> 1) & 3)) << 4));
            CPA16(base + dst, srcs[part] + (size_t)row * H_ + kt * 32 + seg * 8);
        }
        CPA_COMMIT();
    };

    float acc[4][4][4];
    #pragma unroll
    for (int i = 0; i < 4; i++)
        #pragma unroll
        for (int j = 0; j < 4; j++)
            #pragma unroll
            for (int q = 0; q < 4; q++) acc[i][j][q] = 0.0f;

    load_tile(0, 0);

    for (int kt = 0; kt < G2_NT; kt++) {
        const int b = kt & 1;
        if (kt + 1 < G2_NT) { load_tile(kt + 1, 1 - b); CPA_WAIT(1); }
        else                { CPA_WAIT(0); }
        __syncthreads();

        uint32_t stage = sb + b * ST_SZ;
        /* 3 phases: (Ahi,Bhi), (Ahi,Blo), (Alo,Bhi) */
        #pragma unroll
        for (int ph = 0; ph < 3; ph++) {
            uint32_t abase = stage + ((ph == 2) ? ST_ALO : ST_AHI);
            uint32_t bbase = stage + ((ph == 1) ? ST_BLO : ST_BHI);
            #pragma unroll
            for (int kh = 0; kh < 2; kh++) {
                uint32_t af[4][4];
                #pragma unroll
                for (int mt = 0; mt < 4; mt++) {
                    int row = wm + mt * 16 + (lid & 15);
                    int ch  = (kh * 2 + (lid >> 4)) ^ ((row >> 1) & 3);
                    ldm_x4(af[mt][0], af[mt][1], af[mt][2], af[mt][3],
                           abase + (uint32_t)(row * 64 + ch * 16));
                }
                uint32_t bfr[2][4];
                #pragma unroll
                for (int np = 0; np < 2; np++) {
                    int row = wn + np * 16 + ((lid >> 4) * 8) + (lid & 7);
                    int ch  = (kh * 2 + ((lid >> 3) & 1)) ^ ((row >> 1) & 3);
                    ldm_x4(bfr[np][0], bfr[np][1], bfr[np][2], bfr[np][3],
                           bbase + (uint32_t)(row * 64 + ch * 16));
                }
                #pragma unroll
                for (int mt = 0; mt < 4; mt++)
                    #pragma unroll
                    for (int nt = 0; nt < 4; nt++)
                        mma_bf16(acc[mt][nt], af[mt], &bfr[nt >> 1][(nt & 1) * 2]);
            }
        }
        __syncthreads();
    }

    /* epilogue: + bias, direct float2 stores */
    #pragma unroll
    for (int nt = 0; nt < 4; nt++) {
        int col = n0 + wn + nt * 8 + (lid & 3) * 2;
        float bx = __ldg(b2 + 1024 + col);
        float by = __ldg(b2 + 1024 + col + 1);
        #pragma unroll
        for (int mt = 0; mt < 4; mt++) {
            int r0 = m0 + wm + mt * 16 + (lid >> 2);
            float2 v0 = make_float2(acc[mt][nt][0] + bx, acc[mt][nt][1] + by);
            float2 v1 = make_float2(acc[mt][nt][2] + bx, acc[mt][nt][3] + by);
            *reinterpret_cast<float2*>(g_nn + (size_t)r0 * NOUT + col) = v0;
            *reinterpret_cast<float2*>(g_nn + (size_t)(r0 + 8) * NOUT + col) = v1;
        }
    }
}

/* ------------------------------------------------------------------ */
/* Postproc: per (row, c>=32) mixture-CDF math                         */
/* ------------------------------------------------------------------ */
__global__ __launch_bounds__(256) void post_kernel(
    const float* __restrict__ z, const float* __restrict__ mask,
    const float* __restrict__ sfv, const float* __restrict__ msfv,
    float* __restrict__ out)
{
    __shared__ float red[256];
    const int tid = threadIdx.x;
    const int rl = tid >> 5, cl = tid & 31;
    const int row = blockIdx.x * 8 + rl;
    const int c = 32 + cl;

    {
        float mlow = __ldg(mask + cl);
        out[(size_t)row * C_ + cl] = z[(size_t)row * C_ + cl] * mlow;
    }

    float p[32];
    {
        const float* pp = g_nn + (size_t)row * NOUT + cl * 32;
        #pragma unroll
        for (int q = 0; q < 32; q += 4) {
            float4 v = *reinterpret_cast<const float4*>(pp + q);
            p[q] = v.x; p[q+1] = v.y; p[q+2] = v.z; p[q+3] = v.w;
        }
    }

    const float zc = z[(size_t)row * C_ + c];
    const float maskv = __ldg(mask + c);
    const float cm = 1.0f - maskv;

    float sf = expf(__ldg(sfv + c));
    float t  = p[0] * cm;
    float ls = tanhf(p[1] / fmaxf(sf, 1.0f)) * sf * cm;

    float lp[K_], aa[K_], bbk[K_];
    float mx0 = -INFINITY, mxA = -INFINITY, mxB = -INFINITY;
    #pragma unroll
    for (int k = 0; k < K_; k++) { lp[k] = p[2 + k] * cm; mx0 = fmaxf(mx0, lp[k]); }
    #pragma unroll
    for (int k = 0; k < K_; k++) {
        float msf = expf(__ldg(msfv + c * K_ + k));
        float mls = tanhf(p[22 + k] / fmaxf(msf, 1.0f)) * msf * cm;
        float mt  = p[12 + k] * cm;
        float u   = (zc - mt) * expf(-mls);
        float e   = expf(-fabsf(u));
        float l1  = log1pf(e);
        float logsig = fminf(u, 0.0f) - l1;
        float sp     = fmaxf(u, 0.0f) + l1;
        aa[k]  = lp[k] + logsig;
        bbk[k] = lp[k] + u - mls - 2.0f * sp;
        mxA = fmaxf(mxA, aa[k]);
        mxB = fmaxf(mxB, bbk[k]);
    }
    float s0 = 0.0f, sA = 0.0f, sB = 0.0f;
    #pragma unroll
    for (int k = 0; k < K_; k++) {
        s0 += expf(lp[k] - mx0); sA += expf(aa[k] - mxA); sB += expf(bbk[k] - mxB);
    }
    float lse0 = mx0 + logf(s0);
    float lseA = mxA + logf(sA);
    float lseB = mxB + logf(sB);

    float log_cdf = lseA - lse0;
    float p_cdf   = expf(log_cdf);
    float z_logit = -logf(fmaxf(1.0f / p_cdf - 1.0f, 1e-22f));
    float mixt_ldj = -logf(fmaxf(p_cdf, 1e-22f)) - logf(fmaxf(1.0f - p_cdf, 1e-22f));
    float logistic_ldj = lseB - lse0;

    float zo = (z_logit + t) * expf(ls);
    zo = zo * cm + zc * maskv;
    out[(size_t)row * C_ + c] = zo;

    red[tid] = cm * (ls + mixt_ldj + logistic_ldj);
    __syncthreads();
    for (int s = 128; s > 0; s >>= 1) {
        if (tid < s) red[tid] += red[tid + s];
        __syncthreads();
    }
    if (tid == 0) g_part[blockIdx.x] = red[0];
}

__global__ __launch_bounds__(128) void reduce_kernel(float* __restrict__ out)
{
    __shared__ float red[128];
    const int b = blockIdx.x, tid = threadIdx.x;
    red[tid] = g_part[b * 128 + tid];
    __syncthreads();
    for (int s = 64; s > 0; s >>= 1) {
        if (tid < s) red[tid] += red[tid + s];
        __syncthreads();
    }
    if (tid == 0) out[(size_t)M_ * C_ + b] = red[0];
}

extern "C" void kernel_launch(void* const* d_in, const int* in_sizes, int n_in,
                              void* d_out, int out_size)
{
    const float* z    = (const float*)d_in[0];
    const float* mask = (const float*)d_in[1];
    const float* w1   = (const float*)d_in[2];
    const float* b1   = (const float*)d_in[3];
    const float* w2   = (const float*)d_in[4];
    const float* b2   = (const float*)d_in[5];
    const float* sfv  = (const float*)d_in[6];
    const float* msfv = (const float*)d_in[7];
    float* out = (float*)d_out;

    cudaFuncSetAttribute(gemm2_mma_kernel,
                         cudaFuncAttributeMaxDynamicSharedMemorySize, G2_SMEM);

    dim3 gt(NOUT / 32, H_ / 32);
    w2t_kernel<<<gt, 256>>>(w2);

    dim3 g1(H_ / 128, M_ / 64);
    gemm1_kernel<<<g1, 256>>>(z, mask, w1, b1);

    dim3 g2(NOUT / 128, M_ / 128);   /* (8, 128) = 1024 CTAs */
    gemm2_mma_kernel<<<g2, 256, G2_SMEM>>>(b2);

    post_kernel<<<M_ / 8, 256>>>(z, mask, sfv, msfv, out);
    reduce_kernel<<<B_, 128>>>(out);
}